// round 15
// baseline (speedup 1.0000x reference)
#include <cuda_runtime.h>
#include <cuda_bf16.h>
#include <cstdint>

#define Bz 8
#define Tt 12
#define NN 512
#define FIN 32
#define FOUT 64
#define CH 64

// Scratch (device globals; no allocation allowed)
__device__ float g_xtA[Bz*Tt*NN*FIN];
__device__ float g_xtB[Bz*Tt*NN*FIN];
__device__ float g_part[8L*Bz*Tt*NN*FIN];   // partials (final pass only)

// smem layout (bytes)
#define XT_H   0u          // [512 n][stride 40 bf16] (80 B rows)
#define XT_L   40960u
#define U_H    81920u      // [64 m][stride 520 bf16] (1040 B rows, n contiguous)
#define U_L    148480u
#define XPT_H  215040u     // [32 f][stride 72 bf16] (144 B rows, m contiguous)
#define XPT_L  219648u
#define RED    224256u     // ssum[8][64]
#define RS_O   226304u     // rs[64]
#define SMEMSZ 226560u     // 1 CTA/SM, 1024 threads

__device__ __forceinline__ uint32_t bf2(float lo, float hi) {
    uint32_t r; asm("cvt.rn.bf16x2.f32 %0, %1, %2;" : "=r"(r) : "f"(hi), "f"(lo)); return r;
}
__device__ __forceinline__ void mma_bf16(float* d, const uint32_t* a, const uint32_t* b) {
    asm volatile("mma.sync.aligned.m16n8k16.row.col.f32.bf16.bf16.f32 "
        "{%0,%1,%2,%3}, {%4,%5,%6,%7}, {%8,%9}, {%0,%1,%2,%3};"
        : "+f"(d[0]), "+f"(d[1]), "+f"(d[2]), "+f"(d[3])
        : "r"(a[0]), "r"(a[1]), "r"(a[2]), "r"(a[3]), "r"(b[0]), "r"(b[1]));
}
__device__ __forceinline__ void ldmx4(uint32_t* r, uint32_t a) {
    asm volatile("ldmatrix.sync.aligned.m8n8.x4.shared.b16 {%0,%1,%2,%3}, [%4];"
        : "=r"(r[0]), "=r"(r[1]), "=r"(r[2]), "=r"(r[3]) : "r"(a));
}
__device__ __forceinline__ void ldmx4t(uint32_t* r, uint32_t a) {
    asm volatile("ldmatrix.sync.aligned.m8n8.x4.trans.shared.b16 {%0,%1,%2,%3}, [%4];"
        : "=r"(r[0]), "=r"(r[1]), "=r"(r[2]), "=r"(r[3]) : "r"(a));
}
__device__ __forceinline__ uint32_t smem_u32(const void* p) {
    uint32_t a;
    asm("{ .reg .u64 t; cvta.to.shared.u64 t, %1; cvt.u32.u64 %0, t; }" : "=r"(a) : "l"(p));
    return a;
}
// no-return vector reduction into L2 (sm_90+)
__device__ __forceinline__ void red2(float* p, float a, float b) {
    asm volatile("red.global.add.v2.f32 [%0], {%1, %2};" :: "l"(p), "f"(a), "f"(b) : "memory");
}
__device__ __forceinline__ uint32_t xtb(int n, int f) { return (uint32_t)((n*40 + f)*2); }
__device__ __forceinline__ uint32_t xpb(int f, int m) { return (uint32_t)((f*72 + m)*2); }

// ---------------------------------------------------------------------------
__global__ __launch_bounds__(256) void k_transpose(const float* __restrict__ x,
                                                   float* __restrict__ xt) {
    int idx = blockIdx.x * blockDim.x + threadIdx.x;
    if (idx >= Bz*Tt*NN*FIN) return;
    int f = idx & (FIN-1);
    int n = (idx >> 5) & (NN-1);
    int t = (idx / (FIN*NN)) % Tt;
    int b = idx / (FIN*NN*Tt);
    xt[idx] = x[(((long)b*NN + n)*Tt + t)*FIN + f];
}

// ---------------------------------------------------------------------------
// k_zero: dst[t=0] = x[t=0]; dst[t>=1] = 0   (atomic accumulation base;
// the mask*x term is added by chunk-0 CTAs of k_fused from smem)
__global__ __launch_bounds__(512) void k_zero(const float* __restrict__ xsrc,
                                              float* __restrict__ dst) {
    const int b = blockIdx.y, t = blockIdx.x;
    const long base = (long)(b*Tt + t)*NN*FIN;
    float4* d = (float4*)(dst + base);
    if (t == 0) {
        const float4* s = (const float4*)(xsrc + base);
        for (int i = threadIdx.x; i < NN*FIN/4; i += 512) d[i] = s[i];
        return;
    }
    const float4 z = make_float4(0.f, 0.f, 0.f, 0.f);
    for (int i = threadIdx.x; i < NN*FIN/4; i += 512) d[i] = z;
}

// ---------------------------------------------------------------------------
// Fused tensor-core pass, single-score-pass. 1024 threads = 32 warps.
// body mode (adj==null): red.add (1-mask)*partial (+ mask*x on chunk 0) into dstbuf.
// final mode (adj!=null): store partials to part (k_out sums them).
__global__ __launch_bounds__(1024, 1) void k_fused(const float* __restrict__ xsrc,
                                                   const float* __restrict__ phase,
                                                   const float* __restrict__ adj,
                                                   float* __restrict__ part,
                                                   float* __restrict__ dstbuf,
                                                   const float* __restrict__ mask,
                                                   int t_base) {
    extern __shared__ char sm[];
    const uint32_t sb = smem_u32(sm);
    const int tid = threadIdx.x, w = tid >> 5, lane = tid & 31;
    const int g = lane >> 2, q = lane & 3;
    const int b = blockIdx.z, t = blockIdx.y + t_base, c = blockIdx.x;
    const int bt = b*Tt + t;
    const int m0 = c*CH;
    const float isf = 0.17677669529663687f;   // 1/sqrt(32)

    // per-lane ldmatrix offsets
    const int l7 = lane & 7, sel = lane >> 3;
    const uint32_t xtB_lane = ((sel & 2) ? (XT_L - XT_H) : 0u) + (uint32_t)(l7*80) + ((sel & 1) ? 16u : 0u);
    const uint32_t xtA_lane = (uint32_t)((((sel & 1)*8 + l7)) * 80) + ((sel >> 1) ? 16u : 0u);
    const uint32_t xpB_lane = ((sel & 2) ? (XPT_L - XPT_H) : 0u) + (uint32_t)(l7*144) + ((sel & 1) ? 16u : 0u);
    const uint32_t uA_lane  = (uint32_t)(((sel >> 1)*8 + l7)*1040 + (sel & 1)*16);

    // ---- build Xt (hi/lo split, stride 40 halfwords) ----
    const float2* Xg2 = (const float2*)(xsrc + (long)bt*NN*FIN);
    for (int i = tid; i < NN*FIN/2; i += 1024) {
        int n = i >> 4, fp = (i & 15) * 2;
        float2 v = Xg2[i];
        uint32_t h = bf2(v.x, v.y);
        float l0 = v.x - __uint_as_float(h << 16);
        float l1 = v.y - __uint_as_float(h & 0xffff0000u);
        uint32_t l = bf2(l0, l1);
        *(uint32_t*)(sm + XT_H + xtb(n, fp)) = h;
        *(uint32_t*)(sm + XT_L + xtb(n, fp)) = l;
    }
    __syncthreads();

    // ---- resident A fragments: rows mr..mr+16 of Xt (hi & lo planes) ----
    const int mi = w & 3, nq = w >> 2;   // nq in 0..7
    const int mr = m0 + mi*16;
    uint32_t AH[2][4], AL[2][4];
    #pragma unroll
    for (int ks = 0; ks < 2; ++ks) {
        ldmx4(AH[ks], sb + XT_H + (uint32_t)mr*80 + (uint32_t)ks*32 + xtA_lane);
        ldmx4(AL[ks], sb + XT_L + (uint32_t)mr*80 + (uint32_t)ks*32 + xtA_lane);
    }

    const float* P0 = phase + ((long)bt*NN + (mr + g))*NN;
    const float* P1 = P0 + 8*NN;
    const float* A0 = adj ? (adj + (long)(mr + g)*NN) : nullptr;
    const float* A1 = A0 ? (A0 + 8*NN) : nullptr;

    // ---- pass 1: scores once; U = exp*phase; accumulate row sums ----
    float su0 = 0.f, su1 = 0.f;
    const int ml = mi*16 + g;
    #pragma unroll 2
    for (int jj = 0; jj < 8; ++jj) {
        const int noff = nq*64 + jj*8;
        const int n0 = noff + 2*q;
        float2 p0 = *(const float2*)(P0 + n0);
        float2 p1 = *(const float2*)(P1 + n0);
        if (A0) {
            float2 a0v = *(const float2*)(A0 + n0);
            float2 a1v = *(const float2*)(A1 + n0);
            p0.x *= a0v.x; p0.y *= a0v.y;
            p1.x *= a1v.x; p1.y *= a1v.y;
        }
        float d[4] = {0.f,0.f,0.f,0.f}, e[4] = {0.f,0.f,0.f,0.f};
        #pragma unroll
        for (int ks = 0; ks < 2; ++ks) {
            uint32_t bb[4];
            ldmx4(bb, sb + XT_H + (uint32_t)noff*80 + (uint32_t)ks*32 + xtB_lane);
            mma_bf16(d, AH[ks], bb);
            mma_bf16(e, AH[ks], bb + 2);
            mma_bf16(d, AL[ks], bb);
        }
        float ex00 = __expf((d[0]+e[0])*isf);
        float ex01 = __expf((d[1]+e[1])*isf);
        float ex10 = __expf((d[2]+e[2])*isf);
        float ex11 = __expf((d[3]+e[3])*isf);
        su0 += ex00 + ex01;
        su1 += ex10 + ex11;
        float w00 = ex00*p0.x, w01 = ex01*p0.y;
        float w10 = ex10*p1.x, w11 = ex11*p1.y;
        const uint32_t con = (uint32_t)(n0*2);
        uint32_t row0 = (uint32_t)ml*1040, row1 = (uint32_t)(ml+8)*1040;
        uint32_t h0 = bf2(w00, w01);
        float r00 = w00 - __uint_as_float(h0 << 16);
        float r01 = w01 - __uint_as_float(h0 & 0xffff0000u);
        *(uint32_t*)(sm + U_H + row0 + con) = h0;
        *(uint32_t*)(sm + U_L + row0 + con) = bf2(r00, r01);
        uint32_t h1 = bf2(w10, w11);
        float r10 = w10 - __uint_as_float(h1 << 16);
        float r11 = w11 - __uint_as_float(h1 & 0xffff0000u);
        *(uint32_t*)(sm + U_H + row1 + con) = h1;
        *(uint32_t*)(sm + U_L + row1 + con) = bf2(r10, r11);
    }
    #pragma unroll
    for (int off = 1; off <= 2; off <<= 1) {
        su0 += __shfl_xor_sync(0xffffffffu, su0, off);
        su1 += __shfl_xor_sync(0xffffffffu, su1, off);
    }
    float* ssum = (float*)(sm + RED);
    if (q == 0) {
        ssum[nq*64 + ml]     = su0;
        ssum[nq*64 + ml + 8] = su1;
    }
    __syncthreads();

    // ---- rs[m] = isf / rowsum ----
    float* rsv = (float*)(sm + RS_O);
    if (tid < 64) {
        float s = 0.f;
        #pragma unroll
        for (int k = 0; k < 8; ++k) s += ssum[k*64 + tid];
        rsv[tid] = isf / s;
    }
    __syncthreads();

    // ---- build XpT with rs folded in ----
    const int tsrc = adj ? t : t - 1;
    const float* Xpg = xsrc + ((long)(b*Tt + tsrc)*NN + m0)*FIN;
    {
        int i = tid;   // exactly (CH/2)*FIN = 1024
        int mp = i >> 5, f = i & 31;
        float v0 = Xpg[(2*mp)*FIN + f] * rsv[2*mp];
        float v1 = Xpg[(2*mp+1)*FIN + f] * rsv[2*mp+1];
        uint32_t h = bf2(v0, v1);
        float l0 = v0 - __uint_as_float(h << 16);
        float l1 = v1 - __uint_as_float(h & 0xffff0000u);
        *(uint32_t*)(sm + XPT_H + xpb(f, 2*mp)) = h;
        *(uint32_t*)(sm + XPT_L + xpb(f, 2*mp)) = bf2(l0, l1);
    }
    __syncthreads();

    // ---- pass 2: apply. Warp w owns n-tile [16w, 16w+16); loops 4 f-quarters ----
    const int nt = w*16;
    float acc[4][4];
    #pragma unroll
    for (int fq = 0; fq < 4; ++fq)
        #pragma unroll
        for (int i = 0; i < 4; ++i) acc[fq][i] = 0.f;

    #pragma unroll
    for (int ks = 0; ks < 4; ++ks) {
        uint32_t ah[4], al[4];
        ldmx4t(ah, sb + U_H + (uint32_t)ks*16640 + (uint32_t)nt*2 + uA_lane);
        ldmx4t(al, sb + U_L + (uint32_t)ks*16640 + (uint32_t)nt*2 + uA_lane);
        #pragma unroll
        for (int fq = 0; fq < 4; ++fq) {
            uint32_t bb[4];
            ldmx4(bb, sb + XPT_H + (uint32_t)(fq*8)*144 + (uint32_t)ks*32 + xpB_lane);
            mma_bf16(acc[fq], ah, bb);
            mma_bf16(acc[fq], ah, bb + 2);
            mma_bf16(acc[fq], al, bb);
        }
    }

    if (A0) {
        // final mode: store partials (k_out sums the 8 chunks)
        float* dstp = part + (((long)c*(Bz*Tt) + bt)*NN + nt + g)*FIN;
        #pragma unroll
        for (int fq = 0; fq < 4; ++fq) {
            const int f = fq*8 + 2*q;
            *(float2*)(dstp + f)          = make_float2(acc[fq][0], acc[fq][1]);
            *(float2*)(dstp + 8*FIN + f)  = make_float2(acc[fq][2], acc[fq][3]);
        }
    } else {
        // body mode: reduce (1-mask)*partial (+ mask*x on chunk 0) into dstbuf
        const float mk0 = mask[nt + g];
        const float mk1 = mask[nt + 8 + g];
        const float om0 = 1.f - mk0, om1 = 1.f - mk1;
        float* dstp = dstbuf + ((long)bt*NN + nt + g)*FIN;
        #pragma unroll
        for (int fq = 0; fq < 4; ++fq) {
            const int f = fq*8 + 2*q;
            float v00 = acc[fq][0]*om0, v01 = acc[fq][1]*om0;
            float v10 = acc[fq][2]*om1, v11 = acc[fq][3]*om1;
            if (c == 0) {
                // add mask*x from smem Xt (hi+lo reconstruct)
                uint32_t h0 = *(uint32_t*)(sm + XT_H + xtb(nt + g, f));
                uint32_t l0 = *(uint32_t*)(sm + XT_L + xtb(nt + g, f));
                v00 += mk0 * (__uint_as_float(h0 << 16) + __uint_as_float(l0 << 16));
                v01 += mk0 * (__uint_as_float(h0 & 0xffff0000u) + __uint_as_float(l0 & 0xffff0000u));
                uint32_t h1 = *(uint32_t*)(sm + XT_H + xtb(nt + 8 + g, f));
                uint32_t l1 = *(uint32_t*)(sm + XT_L + xtb(nt + 8 + g, f));
                v10 += mk1 * (__uint_as_float(h1 << 16) + __uint_as_float(l1 << 16));
                v11 += mk1 * (__uint_as_float(h1 & 0xffff0000u) + __uint_as_float(l1 & 0xffff0000u));
            }
            red2(dstp + f,          v00, v01);
            red2(dstp + 8*FIN + f,  v10, v11);
        }
    }
}

// ---------------------------------------------------------------------------
__global__ __launch_bounds__(512) void k_out(const float* __restrict__ part,
                                             const float* __restrict__ theta,
                                             float* __restrict__ out) {
    extern __shared__ float smf[];
    float* th = smf;
    float* ag = smf + FIN*FOUT;
    const int b = blockIdx.y, t = blockIdx.x;
    const long base = (long)(b*Tt + t)*NN*FIN;
    const long P = (long)(Bz*Tt)*NN*FIN;
    for (int i = threadIdx.x; i < FIN*FOUT; i += 512) th[i] = theta[i];
    for (int i = threadIdx.x; i < NN*FIN; i += 512) {
        float s = part[base + i];
        #pragma unroll
        for (int cc = 1; cc < 8; ++cc) s += part[cc*P + base + i];
        ag[i] = s;
    }
    __syncthreads();

    const int o = threadIdx.x & 63;
    const int ng = threadIdx.x >> 6;
    for (int nb = 0; nb < 64; ++nb) {
        int n = nb*8 + ng;
        float acc = 0.f;
        #pragma unroll
        for (int f = 0; f < FIN; ++f) acc += ag[n*FIN + f] * th[f*FOUT + o];
        out[(((long)b*NN + n)*Tt + t)*FOUT + o] = fmaxf(acc, 0.f);
    }
}

// ---------------------------------------------------------------------------
extern "C" void kernel_launch(void* const* d_in, const int* in_sizes, int n_in,
                              void* d_out, int out_size) {
    const float* x     = (const float*)d_in[0];
    const float* phase = (const float*)d_in[1];
    const float* adj   = (const float*)d_in[2];
    const float* mask  = (const float*)d_in[3];
    const float* theta = (const float*)d_in[4];
    float* out = (float*)d_out;

    float *xtA, *xtB, *partg;
    cudaGetSymbolAddress((void**)&xtA, g_xtA);
    cudaGetSymbolAddress((void**)&xtB, g_xtB);
    cudaGetSymbolAddress((void**)&partg, g_part);

    const int SM3 = (FIN*FOUT + NN*FIN)*4;
    cudaFuncSetAttribute(k_fused, cudaFuncAttributeMaxDynamicSharedMemorySize, SMEMSZ);
    cudaFuncSetAttribute(k_out,   cudaFuncAttributeMaxDynamicSharedMemorySize, SM3);

    k_transpose<<<(Bz*Tt*NN*FIN + 255)/256, 256>>>(x, xtA);

    float* src = xtA;
    float* dst = xtB;
    for (int it = 0; it < Tt - 1; ++it) {
        k_zero <<<dim3(Tt, Bz), 512>>>(src, dst);
        k_fused<<<dim3(8, Tt-1, Bz), 1024, SMEMSZ>>>(src, phase, nullptr, nullptr, dst, mask, 1);
        float* tmp = src; src = dst; dst = tmp;
    }
    k_fused<<<dim3(8, Tt, Bz), 1024, SMEMSZ>>>(src, phase, adj, partg, nullptr, nullptr, 0);
    k_out<<<dim3(Tt, Bz), 512, SM3>>>(partg, theta, out);
}

// round 16
// speedup vs baseline: 1.1033x; 1.1033x over previous
#include <cuda_runtime.h>
#include <cuda_bf16.h>
#include <cstdint>

#define Bz 8
#define Tt 12
#define NN 512
#define FIN 32
#define FOUT 64
#define CH 64

// Scratch (device globals; no allocation allowed)
__device__ float g_xtA[Bz*Tt*NN*FIN];
__device__ float g_xtB[Bz*Tt*NN*FIN];
__device__ float g_part[8L*Bz*Tt*NN*FIN];   // partials (final pass only)

// smem layout (bytes)
#define XT_H   0u          // [512 n][stride 40 bf16] (80 B rows)
#define XT_L   40960u
#define U_H    81920u      // [64 m][stride 520 bf16] (1040 B rows, n contiguous)
#define U_L    148480u
#define XPT_H  215040u     // [32 f][stride 72 bf16] (144 B rows, m contiguous)
#define XPT_L  219648u
#define RED    224256u     // ssum[8][64]
#define RS_O   226304u     // rs[64]
#define SMEMSZ 226560u     // 1 CTA/SM, 1024 threads

__device__ __forceinline__ uint32_t bf2(float lo, float hi) {
    uint32_t r; asm("cvt.rn.bf16x2.f32 %0, %1, %2;" : "=r"(r) : "f"(hi), "f"(lo)); return r;
}
__device__ __forceinline__ void mma_bf16(float* d, const uint32_t* a, const uint32_t* b) {
    asm volatile("mma.sync.aligned.m16n8k16.row.col.f32.bf16.bf16.f32 "
        "{%0,%1,%2,%3}, {%4,%5,%6,%7}, {%8,%9}, {%0,%1,%2,%3};"
        : "+f"(d[0]), "+f"(d[1]), "+f"(d[2]), "+f"(d[3])
        : "r"(a[0]), "r"(a[1]), "r"(a[2]), "r"(a[3]), "r"(b[0]), "r"(b[1]));
}
__device__ __forceinline__ void ldmx4(uint32_t* r, uint32_t a) {
    asm volatile("ldmatrix.sync.aligned.m8n8.x4.shared.b16 {%0,%1,%2,%3}, [%4];"
        : "=r"(r[0]), "=r"(r[1]), "=r"(r[2]), "=r"(r[3]) : "r"(a));
}
__device__ __forceinline__ void ldmx4t(uint32_t* r, uint32_t a) {
    asm volatile("ldmatrix.sync.aligned.m8n8.x4.trans.shared.b16 {%0,%1,%2,%3}, [%4];"
        : "=r"(r[0]), "=r"(r[1]), "=r"(r[2]), "=r"(r[3]) : "r"(a));
}
__device__ __forceinline__ uint32_t smem_u32(const void* p) {
    uint32_t a;
    asm("{ .reg .u64 t; cvta.to.shared.u64 t, %1; cvt.u32.u64 %0, t; }" : "=r"(a) : "l"(p));
    return a;
}
// no-return vector reduction into L2 (sm_90+)
__device__ __forceinline__ void red2(float* p, float a, float b) {
    asm volatile("red.global.add.v2.f32 [%0], {%1, %2};" :: "l"(p), "f"(a), "f"(b) : "memory");
}
__device__ __forceinline__ uint32_t xtb(int n, int f) { return (uint32_t)((n*40 + f)*2); }
__device__ __forceinline__ uint32_t xpb(int f, int m) { return (uint32_t)((f*72 + m)*2); }

// ---------------------------------------------------------------------------
__global__ __launch_bounds__(256) void k_transpose(const float* __restrict__ x,
                                                   float* __restrict__ xt) {
    int idx = blockIdx.x * blockDim.x + threadIdx.x;
    if (idx >= Bz*Tt*NN*FIN) return;
    int f = idx & (FIN-1);
    int n = (idx >> 5) & (NN-1);
    int t = (idx / (FIN*NN)) % Tt;
    int b = idx / (FIN*NN*Tt);
    xt[idx] = x[(((long)b*NN + n)*Tt + t)*FIN + f];
}

// ---------------------------------------------------------------------------
// k_init (flat 1-D): dst[t=0] = x[t=0]; dst[t>=1] = mask * x[t]
// 768 CTAs x 512 threads, 1 float4 per thread.
__global__ __launch_bounds__(512) void k_init(const float* __restrict__ xsrc,
                                              float* __restrict__ dst,
                                              const float* __restrict__ mask) {
    const int idx = blockIdx.x * 512 + threadIdx.x;     // float4 index
    const int bt = idx >> 12;                           // 4096 float4 per (b,t)
    const int t = bt % Tt;
    const int i = idx & 4095;
    float4 x = ((const float4*)xsrc)[idx];
    if (t != 0) {
        float mk = mask[i >> 3];
        x.x *= mk; x.y *= mk; x.z *= mk; x.w *= mk;
    }
    ((float4*)dst)[idx] = x;
}

// ---------------------------------------------------------------------------
// Fused tensor-core pass, single-score-pass. 1024 threads = 32 warps.
// body mode (adj==null): red.add (1-mask)*partial into dstbuf.
// final mode (adj!=null): store partials to part (k_out sums them).
__global__ __launch_bounds__(1024, 1) void k_fused(const float* __restrict__ xsrc,
                                                   const float* __restrict__ phase,
                                                   const float* __restrict__ adj,
                                                   float* __restrict__ part,
                                                   float* __restrict__ dstbuf,
                                                   const float* __restrict__ mask,
                                                   int t_base) {
    extern __shared__ char sm[];
    const uint32_t sb = smem_u32(sm);
    const int tid = threadIdx.x, w = tid >> 5, lane = tid & 31;
    const int g = lane >> 2, q = lane & 3;
    const int b = blockIdx.z, t = blockIdx.y + t_base, c = blockIdx.x;
    const int bt = b*Tt + t;
    const int m0 = c*CH;
    const float isf = 0.17677669529663687f;   // 1/sqrt(32)

    // per-lane ldmatrix offsets
    const int l7 = lane & 7, sel = lane >> 3;
    const uint32_t xtB_lane = ((sel & 2) ? (XT_L - XT_H) : 0u) + (uint32_t)(l7*80) + ((sel & 1) ? 16u : 0u);
    const uint32_t xtA_lane = (uint32_t)((((sel & 1)*8 + l7)) * 80) + ((sel >> 1) ? 16u : 0u);
    const uint32_t xpB_lane = ((sel & 2) ? (XPT_L - XPT_H) : 0u) + (uint32_t)(l7*144) + ((sel & 1) ? 16u : 0u);
    const uint32_t uA_lane  = (uint32_t)(((sel >> 1)*8 + l7)*1040 + (sel & 1)*16);

    // ---- build Xt (hi/lo split, stride 40 halfwords) ----
    const float2* Xg2 = (const float2*)(xsrc + (long)bt*NN*FIN);
    for (int i = tid; i < NN*FIN/2; i += 1024) {
        int n = i >> 4, fp = (i & 15) * 2;
        float2 v = Xg2[i];
        uint32_t h = bf2(v.x, v.y);
        float l0 = v.x - __uint_as_float(h << 16);
        float l1 = v.y - __uint_as_float(h & 0xffff0000u);
        uint32_t l = bf2(l0, l1);
        *(uint32_t*)(sm + XT_H + xtb(n, fp)) = h;
        *(uint32_t*)(sm + XT_L + xtb(n, fp)) = l;
    }
    __syncthreads();

    // ---- resident A fragments: rows mr..mr+16 of Xt (hi & lo planes) ----
    const int mi = w & 3, nq = w >> 2;   // nq in 0..7
    const int mr = m0 + mi*16;
    uint32_t AH[2][4], AL[2][4];
    #pragma unroll
    for (int ks = 0; ks < 2; ++ks) {
        ldmx4(AH[ks], sb + XT_H + (uint32_t)mr*80 + (uint32_t)ks*32 + xtA_lane);
        ldmx4(AL[ks], sb + XT_L + (uint32_t)mr*80 + (uint32_t)ks*32 + xtA_lane);
    }

    const float* P0 = phase + ((long)bt*NN + (mr + g))*NN;
    const float* P1 = P0 + 8*NN;
    const float* A0 = adj ? (adj + (long)(mr + g)*NN) : nullptr;
    const float* A1 = A0 ? (A0 + 8*NN) : nullptr;

    // ---- pass 1: scores once; U = exp*phase; accumulate row sums ----
    float su0 = 0.f, su1 = 0.f;
    const int ml = mi*16 + g;
    #pragma unroll 2
    for (int jj = 0; jj < 8; ++jj) {
        const int noff = nq*64 + jj*8;
        const int n0 = noff + 2*q;
        float2 p0 = *(const float2*)(P0 + n0);
        float2 p1 = *(const float2*)(P1 + n0);
        if (A0) {
            float2 a0v = *(const float2*)(A0 + n0);
            float2 a1v = *(const float2*)(A1 + n0);
            p0.x *= a0v.x; p0.y *= a0v.y;
            p1.x *= a1v.x; p1.y *= a1v.y;
        }
        float d[4] = {0.f,0.f,0.f,0.f}, e[4] = {0.f,0.f,0.f,0.f};
        #pragma unroll
        for (int ks = 0; ks < 2; ++ks) {
            uint32_t bb[4];
            ldmx4(bb, sb + XT_H + (uint32_t)noff*80 + (uint32_t)ks*32 + xtB_lane);
            mma_bf16(d, AH[ks], bb);
            mma_bf16(e, AH[ks], bb + 2);
            mma_bf16(d, AL[ks], bb);
        }
        float ex00 = __expf((d[0]+e[0])*isf);
        float ex01 = __expf((d[1]+e[1])*isf);
        float ex10 = __expf((d[2]+e[2])*isf);
        float ex11 = __expf((d[3]+e[3])*isf);
        su0 += ex00 + ex01;
        su1 += ex10 + ex11;
        float w00 = ex00*p0.x, w01 = ex01*p0.y;
        float w10 = ex10*p1.x, w11 = ex11*p1.y;
        const uint32_t con = (uint32_t)(n0*2);
        uint32_t row0 = (uint32_t)ml*1040, row1 = (uint32_t)(ml+8)*1040;
        uint32_t h0 = bf2(w00, w01);
        float r00 = w00 - __uint_as_float(h0 << 16);
        float r01 = w01 - __uint_as_float(h0 & 0xffff0000u);
        *(uint32_t*)(sm + U_H + row0 + con) = h0;
        *(uint32_t*)(sm + U_L + row0 + con) = bf2(r00, r01);
        uint32_t h1 = bf2(w10, w11);
        float r10 = w10 - __uint_as_float(h1 << 16);
        float r11 = w11 - __uint_as_float(h1 & 0xffff0000u);
        *(uint32_t*)(sm + U_H + row1 + con) = h1;
        *(uint32_t*)(sm + U_L + row1 + con) = bf2(r10, r11);
    }
    #pragma unroll
    for (int off = 1; off <= 2; off <<= 1) {
        su0 += __shfl_xor_sync(0xffffffffu, su0, off);
        su1 += __shfl_xor_sync(0xffffffffu, su1, off);
    }
    float* ssum = (float*)(sm + RED);
    if (q == 0) {
        ssum[nq*64 + ml]     = su0;
        ssum[nq*64 + ml + 8] = su1;
    }
    __syncthreads();

    // ---- rs[m] = isf / rowsum ----
    float* rsv = (float*)(sm + RS_O);
    if (tid < 64) {
        float s = 0.f;
        #pragma unroll
        for (int k = 0; k < 8; ++k) s += ssum[k*64 + tid];
        rsv[tid] = isf / s;
    }
    __syncthreads();

    // ---- build XpT with rs folded in ----
    const int tsrc = adj ? t : t - 1;
    const float* Xpg = xsrc + ((long)(b*Tt + tsrc)*NN + m0)*FIN;
    {
        int i = tid;   // exactly (CH/2)*FIN = 1024
        int mp = i >> 5, f = i & 31;
        float v0 = Xpg[(2*mp)*FIN + f] * rsv[2*mp];
        float v1 = Xpg[(2*mp+1)*FIN + f] * rsv[2*mp+1];
        uint32_t h = bf2(v0, v1);
        float l0 = v0 - __uint_as_float(h << 16);
        float l1 = v1 - __uint_as_float(h & 0xffff0000u);
        *(uint32_t*)(sm + XPT_H + xpb(f, 2*mp)) = h;
        *(uint32_t*)(sm + XPT_L + xpb(f, 2*mp)) = bf2(l0, l1);
    }
    __syncthreads();

    // ---- pass 2: apply. Warp w owns n-tile [16w, 16w+16); loops 4 f-quarters ----
    const int nt = w*16;
    float acc[4][4];
    #pragma unroll
    for (int fq = 0; fq < 4; ++fq)
        #pragma unroll
        for (int i = 0; i < 4; ++i) acc[fq][i] = 0.f;

    #pragma unroll
    for (int ks = 0; ks < 4; ++ks) {
        uint32_t ah[4], al[4];
        ldmx4t(ah, sb + U_H + (uint32_t)ks*16640 + (uint32_t)nt*2 + uA_lane);
        ldmx4t(al, sb + U_L + (uint32_t)ks*16640 + (uint32_t)nt*2 + uA_lane);
        #pragma unroll
        for (int fq = 0; fq < 4; ++fq) {
            uint32_t bb[4];
            ldmx4(bb, sb + XPT_H + (uint32_t)(fq*8)*144 + (uint32_t)ks*32 + xpB_lane);
            mma_bf16(acc[fq], ah, bb);
            mma_bf16(acc[fq], ah, bb + 2);
            mma_bf16(acc[fq], al, bb);
        }
    }

    if (A0) {
        // final mode: store partials (k_out sums the 8 chunks)
        float* dstp = part + (((long)c*(Bz*Tt) + bt)*NN + nt + g)*FIN;
        #pragma unroll
        for (int fq = 0; fq < 4; ++fq) {
            const int f = fq*8 + 2*q;
            *(float2*)(dstp + f)          = make_float2(acc[fq][0], acc[fq][1]);
            *(float2*)(dstp + 8*FIN + f)  = make_float2(acc[fq][2], acc[fq][3]);
        }
    } else {
        // body mode: reduce (1-mask)*partial directly into dstbuf (L2 atomics)
        float om0 = 1.f - mask[nt + g];
        float om1 = 1.f - mask[nt + 8 + g];
        float* dstp = dstbuf + ((long)bt*NN + nt + g)*FIN;
        #pragma unroll
        for (int fq = 0; fq < 4; ++fq) {
            const int f = fq*8 + 2*q;
            red2(dstp + f,          acc[fq][0]*om0, acc[fq][1]*om0);
            red2(dstp + 8*FIN + f,  acc[fq][2]*om1, acc[fq][3]*om1);
        }
    }
}

// ---------------------------------------------------------------------------
__global__ __launch_bounds__(512) void k_out(const float* __restrict__ part,
                                             const float* __restrict__ theta,
                                             float* __restrict__ out) {
    extern __shared__ float smf[];
    float* th = smf;
    float* ag = smf + FIN*FOUT;
    const int b = blockIdx.y, t = blockIdx.x;
    const long base = (long)(b*Tt + t)*NN*FIN;
    const long P = (long)(Bz*Tt)*NN*FIN;
    for (int i = threadIdx.x; i < FIN*FOUT; i += 512) th[i] = theta[i];
    for (int i = threadIdx.x; i < NN*FIN; i += 512) {
        float s = part[base + i];
        #pragma unroll
        for (int cc = 1; cc < 8; ++cc) s += part[cc*P + base + i];
        ag[i] = s;
    }
    __syncthreads();

    const int o = threadIdx.x & 63;
    const int ng = threadIdx.x >> 6;
    for (int nb = 0; nb < 64; ++nb) {
        int n = nb*8 + ng;
        float acc = 0.f;
        #pragma unroll
        for (int f = 0; f < FIN; ++f) acc += ag[n*FIN + f] * th[f*FOUT + o];
        out[(((long)b*NN + n)*Tt + t)*FOUT + o] = fmaxf(acc, 0.f);
    }
}

// ---------------------------------------------------------------------------
extern "C" void kernel_launch(void* const* d_in, const int* in_sizes, int n_in,
                              void* d_out, int out_size) {
    const float* x     = (const float*)d_in[0];
    const float* phase = (const float*)d_in[1];
    const float* adj   = (const float*)d_in[2];
    const float* mask  = (const float*)d_in[3];
    const float* theta = (const float*)d_in[4];
    float* out = (float*)d_out;

    float *xtA, *xtB, *partg;
    cudaGetSymbolAddress((void**)&xtA, g_xtA);
    cudaGetSymbolAddress((void**)&xtB, g_xtB);
    cudaGetSymbolAddress((void**)&partg, g_part);

    const int SM3 = (FIN*FOUT + NN*FIN)*4;
    cudaFuncSetAttribute(k_fused, cudaFuncAttributeMaxDynamicSharedMemorySize, SMEMSZ);
    cudaFuncSetAttribute(k_out,   cudaFuncAttributeMaxDynamicSharedMemorySize, SM3);

    k_transpose<<<(Bz*Tt*NN*FIN + 255)/256, 256>>>(x, xtA);

    float* src = xtA;
    float* dst = xtB;
    for (int it = 0; it < Tt - 1; ++it) {
        k_init <<<Bz*Tt*NN*FIN/4/512, 512>>>(src, dst, mask);
        k_fused<<<dim3(8, Tt-1, Bz), 1024, SMEMSZ>>>(src, phase, nullptr, nullptr, dst, mask, 1);
        float* tmp = src; src = dst; dst = tmp;
    }
    k_fused<<<dim3(8, Tt, Bz), 1024, SMEMSZ>>>(src, phase, adj, partg, nullptr, nullptr, 0);
    k_out<<<dim3(Tt, Bz), 512, SM3>>>(partg, theta, out);
}